// round 1
// baseline (speedup 1.0000x reference)
#include <cuda_runtime.h>
#include <math.h>

#define B_  16
#define C_  256
#define N_  4096

// Scratch (no allocations allowed in kernel_launch)
__device__ float g_inv1[B_ * C_];
__device__ float g_inv2[B_ * C_];
__device__ float g_M1[B_ * C_ * C_];   // attn1+attn0, then softmax in place
__device__ float g_M2[B_ * C_ * C_];   // attn2+attn00, then softmax in place

// ---------------------------------------------------------------------------
// Kernel A: per-(b,c) inverse L2 norms over N for both inputs
// ---------------------------------------------------------------------------
__global__ __launch_bounds__(256) void k_norm(const float* __restrict__ x1,
                                              const float* __restrict__ x2) {
    const int row = blockIdx.x;                  // b*C + c, 0..4095
    const int tid = threadIdx.x;
    const float4* p1 = reinterpret_cast<const float4*>(x1) + (size_t)row * (N_ / 4);
    const float4* p2 = reinterpret_cast<const float4*>(x2) + (size_t)row * (N_ / 4);
    float s1 = 0.f, s2 = 0.f;
    #pragma unroll 4
    for (int i = tid; i < N_ / 4; i += 256) {
        float4 v = p1[i]; s1 += v.x*v.x + v.y*v.y + v.z*v.z + v.w*v.w;
        float4 w = p2[i]; s2 += w.x*w.x + w.y*w.y + w.z*w.z + w.w*w.w;
    }
    #pragma unroll
    for (int o = 16; o > 0; o >>= 1) {
        s1 += __shfl_down_sync(0xffffffffu, s1, o);
        s2 += __shfl_down_sync(0xffffffffu, s2, o);
    }
    __shared__ float sh1[8], sh2[8];
    if ((tid & 31) == 0) { sh1[tid >> 5] = s1; sh2[tid >> 5] = s2; }
    __syncthreads();
    if (tid == 0) {
        float t1 = 0.f, t2 = 0.f;
        #pragma unroll
        for (int i = 0; i < 8; i++) { t1 += sh1[i]; t2 += sh2[i]; }
        g_inv1[row] = 1.0f / fmaxf(sqrtf(t1), 1e-12f);
        g_inv2[row] = 1.0f / fmaxf(sqrtf(t2), 1e-12f);
    }
}

// ---------------------------------------------------------------------------
// Kernel B: dual-output Gram GEMM.
//   M1[c,d] = sum_n s[c,n] * x11[d,n]
//   M2[c,d] = sum_n s[c,n] * x21[d,n]
// where s = x1*inv1 + x2*inv2 (per c-row), x11 = x1*inv1, x21 = x2*inv2.
// CTA tile: 64(c) x 64(d), K-tile 16, scaling fused into SMEM loads.
// ---------------------------------------------------------------------------
__global__ __launch_bounds__(256) void k_gemm1(const float* __restrict__ x1,
                                               const float* __restrict__ x2) {
    const int b  = blockIdx.z;
    const int c0 = blockIdx.y * 64;
    const int d0 = blockIdx.x * 64;
    const int tid = threadIdx.x;
    const int tx = tid & 15;         // d sub-tile
    const int ty = tid >> 4;         // c sub-tile

    __shared__ __align__(16) float sS[16][68];   // s  tile, [k][c]
    __shared__ __align__(16) float sU[16][68];   // x11 tile, [k][d]
    __shared__ __align__(16) float sV[16][68];   // x21 tile, [k][d]
    __shared__ float iC1[64], iC2[64], iD1[64], iD2[64];

    if (tid < 64) {
        iC1[tid] = g_inv1[b * C_ + c0 + tid];
        iC2[tid] = g_inv2[b * C_ + c0 + tid];
        iD1[tid] = g_inv1[b * C_ + d0 + tid];
        iD2[tid] = g_inv2[b * C_ + d0 + tid];
    }
    __syncthreads();

    const int r  = tid >> 2;     // 0..63 : row within tile
    const int sg = tid & 3;      // 0..3  : k segment (4 floats)

    const float* pc1 = x1 + (size_t)(b * C_ + c0 + r) * N_ + sg * 4;
    const float* pc2 = x2 + (size_t)(b * C_ + c0 + r) * N_ + sg * 4;
    const float* pd1 = x1 + (size_t)(b * C_ + d0 + r) * N_ + sg * 4;
    const float* pd2 = x2 + (size_t)(b * C_ + d0 + r) * N_ + sg * 4;

    const float ic1 = iC1[r], ic2 = iC2[r];
    const float id1 = iD1[r], id2 = iD2[r];

    float acc1[4][4] = {{0.f}}, acc2[4][4] = {{0.f}};

    for (int kt = 0; kt < N_; kt += 16) {
        float4 a1 = *(const float4*)(pc1 + kt);
        float4 a2 = *(const float4*)(pc2 + kt);
        float4 u1 = *(const float4*)(pd1 + kt);
        float4 u2 = *(const float4*)(pd2 + kt);
        __syncthreads();
        sS[sg*4+0][r] = a1.x*ic1 + a2.x*ic2;
        sS[sg*4+1][r] = a1.y*ic1 + a2.y*ic2;
        sS[sg*4+2][r] = a1.z*ic1 + a2.z*ic2;
        sS[sg*4+3][r] = a1.w*ic1 + a2.w*ic2;
        sU[sg*4+0][r] = u1.x*id1;  sU[sg*4+1][r] = u1.y*id1;
        sU[sg*4+2][r] = u1.z*id1;  sU[sg*4+3][r] = u1.w*id1;
        sV[sg*4+0][r] = u2.x*id2;  sV[sg*4+1][r] = u2.y*id2;
        sV[sg*4+2][r] = u2.z*id2;  sV[sg*4+3][r] = u2.w*id2;
        __syncthreads();
        #pragma unroll
        for (int k = 0; k < 16; k++) {
            float4 av = *(const float4*)&sS[k][ty * 4];
            float4 uv = *(const float4*)&sU[k][tx * 4];
            float4 vv = *(const float4*)&sV[k][tx * 4];
            float a[4] = {av.x, av.y, av.z, av.w};
            float u[4] = {uv.x, uv.y, uv.z, uv.w};
            float v[4] = {vv.x, vv.y, vv.z, vv.w};
            #pragma unroll
            for (int i = 0; i < 4; i++)
                #pragma unroll
                for (int j = 0; j < 4; j++) {
                    acc1[i][j] += a[i] * u[j];
                    acc2[i][j] += a[i] * v[j];
                }
        }
    }

    #pragma unroll
    for (int i = 0; i < 4; i++) {
        const int c = c0 + ty * 4 + i;
        float* o1 = g_M1 + (size_t)(b * C_ + c) * C_ + d0 + tx * 4;
        float* o2 = g_M2 + (size_t)(b * C_ + c) * C_ + d0 + tx * 4;
        *(float4*)o1 = make_float4(acc1[i][0], acc1[i][1], acc1[i][2], acc1[i][3]);
        *(float4*)o2 = make_float4(acc2[i][0], acc2[i][1], acc2[i][2], acc2[i][3]);
    }
}

// ---------------------------------------------------------------------------
// Kernel C: row softmax in place (row = 256 elements along d)
// ---------------------------------------------------------------------------
__global__ __launch_bounds__(256) void k_softmax() {
    float* M = (blockIdx.y ? g_M2 : g_M1) + (size_t)blockIdx.x * C_;
    const int tid = threadIdx.x;
    float v = M[tid];

    __shared__ float sh[8];
    __shared__ float bc;

    float m = v;
    #pragma unroll
    for (int o = 16; o > 0; o >>= 1) m = fmaxf(m, __shfl_xor_sync(0xffffffffu, m, o));
    if ((tid & 31) == 0) sh[tid >> 5] = m;
    __syncthreads();
    if (tid == 0) {
        float t = sh[0];
        #pragma unroll
        for (int i = 1; i < 8; i++) t = fmaxf(t, sh[i]);
        bc = t;
    }
    __syncthreads();
    float e = expf(v - bc);
    __syncthreads();                          // protect sh/bc reuse

    float s = e;
    #pragma unroll
    for (int o = 16; o > 0; o >>= 1) s += __shfl_xor_sync(0xffffffffu, s, o);
    if ((tid & 31) == 0) sh[tid >> 5] = s;
    __syncthreads();
    if (tid == 0) {
        float t = 0.f;
        #pragma unroll
        for (int i = 0; i < 8; i++) t += sh[i];
        bc = t;
    }
    __syncthreads();
    M[tid] = e / bc;
}

// ---------------------------------------------------------------------------
// Kernel D: output GEMM + fused residual epilogue.
//   yT[n,q] = sum_d A1[q,d]*x1[d,n] + A2[q,d]*x2[d,n]
//   out.flat[b, n*C+q] = yT[n,q] + x1.flat + x2.flat
// CTA tile: 128(n) x 64(q), K = 256 in tiles of 16.
// ---------------------------------------------------------------------------
__global__ __launch_bounds__(256) void k_out(const float* __restrict__ x1,
                                             const float* __restrict__ x2,
                                             float* __restrict__ out) {
    const int b  = blockIdx.z;
    const int q0 = blockIdx.y * 64;
    const int n0 = blockIdx.x * 128;
    const int tid = threadIdx.x;
    const int tn = tid & 15;        // n sub-tile (two groups of 4)
    const int tq = tid >> 4;        // q sub-tile (4 consecutive)

    __shared__ __align__(16) float sA1[16][68];    // [k][q]
    __shared__ __align__(16) float sA2[16][68];
    __shared__ __align__(16) float sX1[16][128];   // [k][n]
    __shared__ __align__(16) float sX2[16][128];

    const int r  = tid >> 2;
    const int sg = tid & 3;
    const float* pa1 = g_M1 + (size_t)(b * C_ + q0 + r) * C_ + sg * 4;
    const float* pa2 = g_M2 + (size_t)(b * C_ + q0 + r) * C_ + sg * 4;

    float acc[8][4] = {{0.f}};

    for (int kt = 0; kt < C_; kt += 16) {
        float4 a1 = *(const float4*)(pa1 + kt);
        float4 a2 = *(const float4*)(pa2 + kt);
        float4 xv[2], yv[2];
        #pragma unroll
        for (int i = 0; i < 2; i++) {
            const int idx = tid + i * 256;        // 0..511
            const int kk = idx >> 5;              // 0..15
            const int nc = (idx & 31) * 4;        // 0..124
            const size_t goff = (size_t)(b * C_ + kt + kk) * N_ + n0 + nc;
            xv[i] = *(const float4*)(x1 + goff);
            yv[i] = *(const float4*)(x2 + goff);
        }
        __syncthreads();
        sA1[sg*4+0][r] = a1.x; sA1[sg*4+1][r] = a1.y;
        sA1[sg*4+2][r] = a1.z; sA1[sg*4+3][r] = a1.w;
        sA2[sg*4+0][r] = a2.x; sA2[sg*4+1][r] = a2.y;
        sA2[sg*4+2][r] = a2.z; sA2[sg*4+3][r] = a2.w;
        #pragma unroll
        for (int i = 0; i < 2; i++) {
            const int idx = tid + i * 256;
            const int kk = idx >> 5;
            const int nc = (idx & 31) * 4;
            *(float4*)&sX1[kk][nc] = xv[i];
            *(float4*)&sX2[kk][nc] = yv[i];
        }
        __syncthreads();
        #pragma unroll
        for (int k = 0; k < 16; k++) {
            float4 q1 = *(const float4*)&sA1[k][tq * 4];
            float4 q2 = *(const float4*)&sA2[k][tq * 4];
            float4 u0 = *(const float4*)&sX1[k][tn * 4];
            float4 u1 = *(const float4*)&sX1[k][64 + tn * 4];
            float4 w0 = *(const float4*)&sX2[k][tn * 4];
            float4 w1 = *(const float4*)&sX2[k][64 + tn * 4];
            float xn[8] = {u0.x,u0.y,u0.z,u0.w, u1.x,u1.y,u1.z,u1.w};
            float yn[8] = {w0.x,w0.y,w0.z,w0.w, w1.x,w1.y,w1.z,w1.w};
            float qa[4] = {q1.x,q1.y,q1.z,q1.w};
            float qb[4] = {q2.x,q2.y,q2.z,q2.w};
            #pragma unroll
            for (int i = 0; i < 8; i++)
                #pragma unroll
                for (int j = 0; j < 4; j++)
                    acc[i][j] += xn[i] * qa[j] + yn[i] * qb[j];
        }
    }

    #pragma unroll
    for (int i = 0; i < 8; i++) {
        const int nloc = (i < 4) ? (tn * 4 + i) : (64 + tn * 4 + (i - 4));
        const size_t base = ((size_t)b << 20) + (size_t)(n0 + nloc) * C_ + q0 + tq * 4;
        float4 xa = *(const float4*)(x1 + base);
        float4 xb = *(const float4*)(x2 + base);
        float4 o;
        o.x = acc[i][0] + xa.x + xb.x;
        o.y = acc[i][1] + xa.y + xb.y;
        o.z = acc[i][2] + xa.z + xb.z;
        o.w = acc[i][3] + xa.w + xb.w;
        *(float4*)(out + base) = o;
    }
}

// ---------------------------------------------------------------------------
extern "C" void kernel_launch(void* const* d_in, const int* in_sizes, int n_in,
                              void* d_out, int out_size) {
    const float* x1 = (const float*)d_in[0];
    const float* x2 = (const float*)d_in[1];
    float* out = (float*)d_out;

    k_norm<<<B_ * C_, 256>>>(x1, x2);

    dim3 gB(4, 4, B_);
    k_gemm1<<<gB, 256>>>(x1, x2);

    dim3 gC(B_ * C_, 2);
    k_softmax<<<gC, 256>>>();

    dim3 gD(N_ / 128, C_ / 64, B_);
    k_out<<<gD, 256>>>(x1, x2, out);
}

// round 4
// speedup vs baseline: 5.8091x; 5.8091x over previous
#include <cuda_runtime.h>
#include <cuda_bf16.h>
#include <math.h>
#include <stdint.h>

#define Bb 16
#define Cc 256
#define Nn 4096

// ---------------------------------------------------------------------------
// Global scratch
// ---------------------------------------------------------------------------
__device__ float g_inv1[Bb * Cc];
__device__ float g_inv2[Bb * Cc];
__device__ __nv_bfloat16 g_S [Bb * Cc * Nn];   // s = x1*inv1 + x2*inv2
__device__ __nv_bfloat16 g_X1[Bb * Cc * Nn];   // bf16(x1)
__device__ __nv_bfloat16 g_X2[Bb * Cc * Nn];   // bf16(x2)
__device__ float g_L1[Bb * Cc * Cc];           // logits1
__device__ float g_L2[Bb * Cc * Cc];           // logits2
__device__ __nv_bfloat16 g_A1[Bb * Cc * Cc];   // softmax(logits1) bf16
__device__ __nv_bfloat16 g_A2[Bb * Cc * Cc];

// ---------------------------------------------------------------------------
// PTX helpers (portable: sm_80-era instructions only, no 'a' features)
// ---------------------------------------------------------------------------
__device__ __forceinline__ uint32_t smem_u32(const void* p) {
    uint32_t a;
    asm("{ .reg .u64 t; cvta.to.shared.u64 t, %1; cvt.u32.u64 %0, t; }"
        : "=r"(a) : "l"(p));
    return a;
}

__device__ __forceinline__ void mma16816(float* d, const uint32_t* a, const uint32_t* b) {
    asm volatile("mma.sync.aligned.m16n8k16.row.col.f32.bf16.bf16.f32 "
        "{%0,%1,%2,%3}, {%4,%5,%6,%7}, {%8,%9}, {%0,%1,%2,%3};"
        : "+f"(d[0]), "+f"(d[1]), "+f"(d[2]), "+f"(d[3])
        : "r"(a[0]), "r"(a[1]), "r"(a[2]), "r"(a[3]), "r"(b[0]), "r"(b[1]));
}

__device__ __forceinline__ void ldsm4(uint32_t* r, uint32_t addr) {
    asm volatile("ldmatrix.sync.aligned.m8n8.x4.shared.b16 {%0,%1,%2,%3}, [%4];"
        : "=r"(r[0]), "=r"(r[1]), "=r"(r[2]), "=r"(r[3]) : "r"(addr));
}

__device__ __forceinline__ void ldsm4t(uint32_t* r, uint32_t addr) {
    asm volatile("ldmatrix.sync.aligned.m8n8.x4.trans.shared.b16 {%0,%1,%2,%3}, [%4];"
        : "=r"(r[0]), "=r"(r[1]), "=r"(r[2]), "=r"(r[3]) : "r"(addr));
}

#define CP16(dst, src) \
    asm volatile("cp.async.cg.shared.global [%0], [%1], 16;" \
        :: "r"(dst), "l"(src) : "memory")
#define CP_COMMIT() asm volatile("cp.async.commit_group;" ::: "memory")
#define CP_WAIT1()  asm volatile("cp.async.wait_group 1;"  ::: "memory")

// XOR swizzle for 128B-row tiles: 16B chunk c at row r -> c ^ (r & 7)
__device__ __forceinline__ uint32_t swz(int row, int chunk) {
    return (uint32_t)(row * 128 + ((chunk ^ (row & 7)) << 4));
}

__device__ __forceinline__ uint32_t pk(float lo, float hi) {
    __nv_bfloat162 t = __floats2bfloat162_rn(lo, hi);
    return *reinterpret_cast<uint32_t*>(&t);
}

// ---------------------------------------------------------------------------
// Kernel 1: norms + bf16 materialization
// ---------------------------------------------------------------------------
__global__ __launch_bounds__(256) void k_prep(const float* __restrict__ x1,
                                              const float* __restrict__ x2) {
    const int row = blockIdx.x, tid = threadIdx.x;
    const float4* p1 = reinterpret_cast<const float4*>(x1) + (size_t)row * (Nn / 4);
    const float4* p2 = reinterpret_cast<const float4*>(x2) + (size_t)row * (Nn / 4);
    float s1 = 0.f, s2 = 0.f;
    #pragma unroll
    for (int i = 0; i < 4; i++) {
        float4 v = p1[tid + i * 256]; s1 += v.x*v.x + v.y*v.y + v.z*v.z + v.w*v.w;
        float4 w = p2[tid + i * 256]; s2 += w.x*w.x + w.y*w.y + w.z*w.z + w.w*w.w;
    }
    #pragma unroll
    for (int o = 16; o > 0; o >>= 1) {
        s1 += __shfl_down_sync(0xffffffffu, s1, o);
        s2 += __shfl_down_sync(0xffffffffu, s2, o);
    }
    __shared__ float sh1[8], sh2[8], bi1, bi2;
    if ((tid & 31) == 0) { sh1[tid >> 5] = s1; sh2[tid >> 5] = s2; }
    __syncthreads();
    if (tid == 0) {
        float t1 = 0.f, t2 = 0.f;
        #pragma unroll
        for (int i = 0; i < 8; i++) { t1 += sh1[i]; t2 += sh2[i]; }
        bi1 = 1.0f / fmaxf(sqrtf(t1), 1e-12f);
        bi2 = 1.0f / fmaxf(sqrtf(t2), 1e-12f);
        g_inv1[row] = bi1; g_inv2[row] = bi2;
    }
    __syncthreads();
    const float i1 = bi1, i2 = bi2;
    uint4* oS  = reinterpret_cast<uint4*>(g_S  + (size_t)row * Nn);
    uint4* oX1 = reinterpret_cast<uint4*>(g_X1 + (size_t)row * Nn);
    uint4* oX2 = reinterpret_cast<uint4*>(g_X2 + (size_t)row * Nn);
    #pragma unroll
    for (int i = 0; i < 2; i++) {
        int seg = tid + i * 256;                 // 0..511, 8 elems each
        float4 a = p1[seg * 2], b = p1[seg * 2 + 1];
        float4 c = p2[seg * 2], d = p2[seg * 2 + 1];
        uint4 u1 = { pk(a.x, a.y), pk(a.z, a.w), pk(b.x, b.y), pk(b.z, b.w) };
        uint4 u2 = { pk(c.x, c.y), pk(c.z, c.w), pk(d.x, d.y), pk(d.z, d.w) };
        uint4 us = { pk(a.x*i1 + c.x*i2, a.y*i1 + c.y*i2),
                     pk(a.z*i1 + c.z*i2, a.w*i1 + c.w*i2),
                     pk(b.x*i1 + d.x*i2, b.y*i1 + d.y*i2),
                     pk(b.z*i1 + d.z*i2, b.w*i1 + d.w*i2) };
        oX1[seg] = u1; oX2[seg] = u2; oS[seg] = us;
    }
}

// ---------------------------------------------------------------------------
// Kernel 2: GEMM1 via mma.sync. CTA tile 128(c) x 64(d), K = 4096, KT = 64.
//   D1[c,d] = sum_n S[c,n]*X1[d,n];  L1 = D1*inv1[d]  (likewise D2/L2)
// 3-stage cp.async pipeline; stage = A(16KB) + B1(8KB) + B2(8KB) = 32KB.
// 8 warps: 4 over c (32 rows), 2 over d (32 cols).
// ---------------------------------------------------------------------------
#define G1_STAGE 32768
#define G1_SMEM  (3 * G1_STAGE + 512)

__global__ __launch_bounds__(256, 2) void k_gemm1() {
    extern __shared__ __align__(128) char smem[];
    const uint32_t sb = smem_u32(smem);
    const int tid = threadIdx.x, lane = tid & 31, wid = tid >> 5;
    const int wc = wid >> 1, wd = wid & 1;
    const int b = blockIdx.z, c0 = blockIdx.y * 128, d0 = blockIdx.x * 64;

    float* invs = (float*)(smem + 3 * G1_STAGE);   // [2][64]
    if (tid < 64) {
        invs[tid]      = g_inv1[b * Cc + d0 + tid];
        invs[64 + tid] = g_inv2[b * Cc + d0 + tid];
    }

    const char* gS = (const char*)(g_S  + (size_t)(b * Cc + c0) * Nn);
    const char* gU = (const char*)(g_X1 + (size_t)(b * Cc + d0) * Nn);
    const char* gV = (const char*)(g_X2 + (size_t)(b * Cc + d0) * Nn);

    // stage load: A 1024 chunks (4/thread), B1/B2 512 chunks (2/thread each)
    #define G1_LOAD(st, kt) do { \
        uint32_t s_ = sb + (uint32_t)(st) * G1_STAGE; \
        _Pragma("unroll") \
        for (int i_ = 0; i_ < 4; i_++) { \
            int id_ = i_ * 256 + tid, r_ = id_ >> 3, c_ = id_ & 7; \
            CP16(s_ + swz(r_, c_), gS + (size_t)r_ * 8192 + (size_t)(kt) * 128 + c_ * 16); \
        } \
        _Pragma("unroll") \
        for (int i_ = 0; i_ < 2; i_++) { \
            int id_ = i_ * 256 + tid, r_ = id_ >> 3, c_ = id_ & 7; \
            CP16(s_ + 16384 + swz(r_, c_), gU + (size_t)r_ * 8192 + (size_t)(kt) * 128 + c_ * 16); \
            CP16(s_ + 24576 + swz(r_, c_), gV + (size_t)r_ * 8192 + (size_t)(kt) * 128 + c_ * 16); \
        } \
    } while (0)

    float acc[2][2][4][4];
    #pragma unroll
    for (int o = 0; o < 2; o++)
        #pragma unroll
        for (int m = 0; m < 2; m++)
            #pragma unroll
            for (int n = 0; n < 4; n++)
                #pragma unroll
                for (int k = 0; k < 4; k++) acc[o][m][n][k] = 0.f;

    G1_LOAD(0, 0); CP_COMMIT();
    G1_LOAD(1, 1); CP_COMMIT();
    CP_WAIT1();
    __syncthreads();

    for (int it = 0; it < 64; it++) {
        const uint32_t stg = sb + (uint32_t)(it % 3) * G1_STAGE;
        #pragma unroll
        for (int ks = 0; ks < 4; ks++) {
            uint32_t a[2][4], b1f[4][2], b2f[4][2], r4[4];
            const int ch = ks * 2 + (lane >> 4);
            #pragma unroll
            for (int mt = 0; mt < 2; mt++) {
                int row = wc * 32 + mt * 16 + (lane & 15);
                ldsm4(a[mt], stg + swz(row, ch));
            }
            #pragma unroll
            for (int p = 0; p < 2; p++) {
                int row = wd * 32 + p * 16 + (lane & 15);
                ldsm4(r4, stg + 16384 + swz(row, ch));
                b1f[2*p][0] = r4[0]; b1f[2*p][1] = r4[2];
                b1f[2*p+1][0] = r4[1]; b1f[2*p+1][1] = r4[3];
                ldsm4(r4, stg + 24576 + swz(row, ch));
                b2f[2*p][0] = r4[0]; b2f[2*p][1] = r4[2];
                b2f[2*p+1][0] = r4[1]; b2f[2*p+1][1] = r4[3];
            }
            #pragma unroll
            for (int mt = 0; mt < 2; mt++)
                #pragma unroll
                for (int nt = 0; nt < 4; nt++) {
                    mma16816(acc[0][mt][nt], a[mt], b1f[nt]);
                    mma16816(acc[1][mt][nt], a[mt], b2f[nt]);
                }
        }
        if (it + 2 < 64) G1_LOAD((it + 2) % 3, it + 2);
        CP_COMMIT();
        CP_WAIT1();
        __syncthreads();
    }

    // epilogue: scale by inv[d], write fp32 logits
    const int crow = b * Cc + c0 + wc * 32 + (lane >> 2);
    #pragma unroll
    for (int o = 0; o < 2; o++) {
        float* L = o ? g_L2 : g_L1;
        #pragma unroll
        for (int mt = 0; mt < 2; mt++)
            #pragma unroll
            for (int nt = 0; nt < 4; nt++) {
                int dl = wd * 32 + nt * 8 + (lane & 3) * 2;
                float s0 = invs[o * 64 + dl], s1 = invs[o * 64 + dl + 1];
                float* p = L + (size_t)(crow + mt * 16) * Cc + d0 + dl;
                *(float2*)p = make_float2(acc[o][mt][nt][0] * s0, acc[o][mt][nt][1] * s1);
                *(float2*)(p + 8 * Cc) = make_float2(acc[o][mt][nt][2] * s0, acc[o][mt][nt][3] * s1);
            }
    }
    #undef G1_LOAD
}

// ---------------------------------------------------------------------------
// Kernel 3: softmax fp32 logits -> bf16 attn
// ---------------------------------------------------------------------------
__global__ __launch_bounds__(256) void k_softmax() {
    const int row = blockIdx.x, tid = threadIdx.x;
    const float* L = (blockIdx.y ? g_L2 : g_L1) + (size_t)row * Cc;
    __nv_bfloat16* A = (blockIdx.y ? g_A2 : g_A1) + (size_t)row * Cc;
    float v = L[tid];
    __shared__ float sh[8], bc;
    float m = v;
    #pragma unroll
    for (int o = 16; o > 0; o >>= 1) m = fmaxf(m, __shfl_xor_sync(0xffffffffu, m, o));
    if ((tid & 31) == 0) sh[tid >> 5] = m;
    __syncthreads();
    if (tid == 0) {
        float t = sh[0];
        #pragma unroll
        for (int i = 1; i < 8; i++) t = fmaxf(t, sh[i]);
        bc = t;
    }
    __syncthreads();
    float e = expf(v - bc);
    __syncthreads();
    float s = e;
    #pragma unroll
    for (int o = 16; o > 0; o >>= 1) s += __shfl_xor_sync(0xffffffffu, s, o);
    if ((tid & 31) == 0) sh[tid >> 5] = s;
    __syncthreads();
    if (tid == 0) {
        float t = 0.f;
        #pragma unroll
        for (int i = 0; i < 8; i++) t += sh[i];
        bc = t;
    }
    __syncthreads();
    A[tid] = __float2bfloat16(e / bc);
}

// ---------------------------------------------------------------------------
// Kernel 4: GEMM2 via mma.sync. CTA tile 128(q) x 128(n), K = 256, KT = 64.
//   D[q,n] = sum_d A1[q,d]*X1[d,n] + A2[q,d]*X2[d,n]   (y1+y2 in one acc)
//   out[b, n*256 + q] = D + x1 + x2   (transpose via SMEM restage)
// Stage = A1(16K) + A2(16K) + X1(16K as [2 half][64 d][64 n]) + X2(16K) = 64KB.
// 8 warps: 4 over q (32 rows), 2 over n (64 cols = the n-half).
// ---------------------------------------------------------------------------
#define G2_STAGE 65536
#define G2_SMEM  (3 * G2_STAGE)

__global__ __launch_bounds__(256, 1) void k_gemm2(const float* __restrict__ x1,
                                                  const float* __restrict__ x2,
                                                  float* __restrict__ out) {
    extern __shared__ __align__(128) char smem[];
    const uint32_t sb = smem_u32(smem);
    const int tid = threadIdx.x, lane = tid & 31, wid = tid >> 5;
    const int wq = wid >> 1, wn = wid & 1;
    const int b = blockIdx.z, q0 = blockIdx.y * 128, n0 = blockIdx.x * 128;

    const char* gA1 = (const char*)(g_A1 + (size_t)(b * Cc + q0) * Cc);
    const char* gA2 = (const char*)(g_A2 + (size_t)(b * Cc + q0) * Cc);
    const char* gX1 = (const char*)(g_X1 + (size_t)(b * Cc) * Nn) + (size_t)n0 * 2;
    const char* gX2 = (const char*)(g_X2 + (size_t)(b * Cc) * Nn) + (size_t)n0 * 2;

    #define G2_LOAD(st, kt) do { \
        uint32_t s_ = sb + (uint32_t)(st) * G2_STAGE; \
        _Pragma("unroll") \
        for (int i_ = 0; i_ < 4; i_++) { \
            int id_ = i_ * 256 + tid, r_ = id_ >> 3, c_ = id_ & 7; \
            size_t go_ = (size_t)r_ * 512 + (size_t)(kt) * 128 + c_ * 16; \
            CP16(s_ + swz(r_, c_), gA1 + go_); \
            CP16(s_ + 16384 + swz(r_, c_), gA2 + go_); \
        } \
        _Pragma("unroll") \
        for (int i_ = 0; i_ < 4; i_++) { \
            int id_ = i_ * 256 + tid, d_ = id_ >> 4, nc_ = id_ & 15; \
            size_t go_ = (size_t)((kt) * 64 + d_) * 8192 + nc_ * 16; \
            uint32_t so_ = (uint32_t)((nc_ >> 3) * 8192) + swz(d_, nc_ & 7); \
            CP16(s_ + 32768 + so_, gX1 + go_); \
            CP16(s_ + 49152 + so_, gX2 + go_); \
        } \
    } while (0)

    float acc[2][8][4];
    #pragma unroll
    for (int m = 0; m < 2; m++)
        #pragma unroll
        for (int n = 0; n < 8; n++)
            #pragma unroll
            for (int k = 0; k < 4; k++) acc[m][n][k] = 0.f;

    G2_LOAD(0, 0); CP_COMMIT();
    G2_LOAD(1, 1); CP_COMMIT();
    CP_WAIT1();
    __syncthreads();

    for (int it = 0; it < 4; it++) {
        const uint32_t stg = sb + (uint32_t)(it % 3) * G2_STAGE;
        const uint32_t xh = stg + 32768 + (uint32_t)wn * 8192;   // this warp's n-half
        #pragma unroll
        for (int ks = 0; ks < 4; ks++) {
            uint32_t a1[2][4], a2[2][4], bx1[8][2], bx2[8][2], r4[4];
            const int ch = ks * 2 + (lane >> 4);
            #pragma unroll
            for (int mt = 0; mt < 2; mt++) {
                int row = wq * 32 + mt * 16 + (lane & 15);
                ldsm4(a1[mt], stg + swz(row, ch));
                ldsm4(a2[mt], stg + 16384 + swz(row, ch));
            }
            #pragma unroll
            for (int p = 0; p < 4; p++) {
                int drow = ks * 16 + (lane & 15);
                int xch = 2 * p + (lane >> 4);
                ldsm4t(r4, xh + swz(drow, xch));
                bx1[2*p][0] = r4[0]; bx1[2*p][1] = r4[1];
                bx1[2*p+1][0] = r4[2]; bx1[2*p+1][1] = r4[3];
                ldsm4t(r4, xh + 16384 + swz(drow, xch));
                bx2[2*p][0] = r4[0]; bx2[2*p][1] = r4[1];
                bx2[2*p+1][0] = r4[2]; bx2[2*p+1][1] = r4[3];
            }
            #pragma unroll
            for (int mt = 0; mt < 2; mt++)
                #pragma unroll
                for (int nt = 0; nt < 8; nt++) {
                    mma16816(acc[mt][nt], a1[mt], bx1[nt]);
                    mma16816(acc[mt][nt], a2[mt], bx2[nt]);
                }
        }
        if (it + 2 < 4) G2_LOAD((it + 2) % 3, it + 2);
        CP_COMMIT();
        CP_WAIT1();
        __syncthreads();
    }

    // epilogue: restage D as [n][q] in SMEM (two 64-n halves), fuse residual,
    // write coalesced fp32 rows out[(n)*256 + q0..q0+127].
    float* eps = (float*)smem;                    // [64][132]
    #pragma unroll 1
    for (int h = 0; h < 2; h++) {
        __syncthreads();
        if (wn == h) {
            #pragma unroll
            for (int mt = 0; mt < 2; mt++)
                #pragma unroll
                for (int nt = 0; nt < 8; nt++) {
                    int qL = wq * 32 + mt * 16 + (lane >> 2);
                    int rn = nt * 8 + (lane & 3) * 2;
                    eps[rn * 132 + qL]           = acc[mt][nt][0];
                    eps[(rn + 1) * 132 + qL]     = acc[mt][nt][1];
                    eps[rn * 132 + qL + 8]       = acc[mt][nt][2];
                    eps[(rn + 1) * 132 + qL + 8] = acc[mt][nt][3];
                }
        }
        __syncthreads();
        #pragma unroll
        for (int i = 0; i < 8; i++) {
            int slot = tid + i * 256;             // 0..2047
            int row = slot >> 5, qi = slot & 31;
            size_t idx = ((size_t)b << 20) + (size_t)(n0 + h * 64 + row) * 256 + q0 + qi * 4;
            float4 d4 = *(const float4*)&eps[row * 132 + qi * 4];
            float4 ra = *(const float4*)(x1 + idx);
            float4 rb = *(const float4*)(x2 + idx);
            d4.x += ra.x + rb.x; d4.y += ra.y + rb.y;
            d4.z += ra.z + rb.z; d4.w += ra.w + rb.w;
            *(float4*)(out + idx) = d4;
        }
    }
    #undef G2_LOAD
}

// ---------------------------------------------------------------------------
extern "C" void kernel_launch(void* const* d_in, const int* in_sizes, int n_in,
                              void* d_out, int out_size) {
    const float* x1 = (const float*)d_in[0];
    const float* x2 = (const float*)d_in[1];
    float* out = (float*)d_out;

    cudaFuncSetAttribute(k_gemm1, cudaFuncAttributeMaxDynamicSharedMemorySize, G1_SMEM);
    cudaFuncSetAttribute(k_gemm2, cudaFuncAttributeMaxDynamicSharedMemorySize, G2_SMEM);

    k_prep<<<Bb * Cc, 256>>>(x1, x2);
    k_gemm1<<<dim3(4, 2, Bb), 256, G1_SMEM>>>();
    k_softmax<<<dim3(Bb * Cc, 2), 256>>>();
    k_gemm2<<<dim3(Nn / 128, 2, Bb), 256, G2_SMEM>>>(x1, x2, out);
}

// round 5
// speedup vs baseline: 6.3796x; 1.0982x over previous
#include <cuda_runtime.h>
#include <cuda_bf16.h>
#include <math.h>
#include <stdint.h>

#define Bb 16
#define Cc 256
#define Nn 4096

// ---------------------------------------------------------------------------
// Global scratch
// ---------------------------------------------------------------------------
__device__ float g_inv1[Bb * Cc];
__device__ float g_inv2[Bb * Cc];
__device__ __nv_bfloat16 g_S [Bb * Cc * Nn];   // s = x1*inv1 + x2*inv2
__device__ __nv_bfloat16 g_X1[Bb * Cc * Nn];   // bf16(x1)
__device__ __nv_bfloat16 g_X2[Bb * Cc * Nn];   // bf16(x2)
__device__ float g_L1 [Bb * Cc * Cc];          // logits1 partial (khalf 0)
__device__ float g_L2 [Bb * Cc * Cc];
__device__ float g_L1b[Bb * Cc * Cc];          // logits1 partial (khalf 1)
__device__ float g_L2b[Bb * Cc * Cc];
__device__ __nv_bfloat16 g_A1[Bb * Cc * Cc];   // softmax bf16
__device__ __nv_bfloat16 g_A2[Bb * Cc * Cc];

// ---------------------------------------------------------------------------
// PTX helpers (portable sm_80-era only)
// ---------------------------------------------------------------------------
__device__ __forceinline__ uint32_t smem_u32(const void* p) {
    uint32_t a;
    asm("{ .reg .u64 t; cvta.to.shared.u64 t, %1; cvt.u32.u64 %0, t; }"
        : "=r"(a) : "l"(p));
    return a;
}

__device__ __forceinline__ void mma16816(float* d, const uint32_t* a, const uint32_t* b) {
    asm volatile("mma.sync.aligned.m16n8k16.row.col.f32.bf16.bf16.f32 "
        "{%0,%1,%2,%3}, {%4,%5,%6,%7}, {%8,%9}, {%0,%1,%2,%3};"
        : "+f"(d[0]), "+f"(d[1]), "+f"(d[2]), "+f"(d[3])
        : "r"(a[0]), "r"(a[1]), "r"(a[2]), "r"(a[3]), "r"(b[0]), "r"(b[1]));
}

__device__ __forceinline__ void ldsm4(uint32_t* r, uint32_t addr) {
    asm volatile("ldmatrix.sync.aligned.m8n8.x4.shared.b16 {%0,%1,%2,%3}, [%4];"
        : "=r"(r[0]), "=r"(r[1]), "=r"(r[2]), "=r"(r[3]) : "r"(addr));
}

__device__ __forceinline__ void ldsm4t(uint32_t* r, uint32_t addr) {
    asm volatile("ldmatrix.sync.aligned.m8n8.x4.trans.shared.b16 {%0,%1,%2,%3}, [%4];"
        : "=r"(r[0]), "=r"(r[1]), "=r"(r[2]), "=r"(r[3]) : "r"(addr));
}

#define CP16(dst, src) \
    asm volatile("cp.async.cg.shared.global [%0], [%1], 16;" \
        :: "r"(dst), "l"(src) : "memory")
#define CP_COMMIT() asm volatile("cp.async.commit_group;" ::: "memory")
#define CP_WAIT1()  asm volatile("cp.async.wait_group 1;"  ::: "memory")
#define CP_WAIT0()  asm volatile("cp.async.wait_group 0;"  ::: "memory")

// XOR swizzle for 128B-row tiles
__device__ __forceinline__ uint32_t swz(int row, int chunk) {
    return (uint32_t)(row * 128 + ((chunk ^ (row & 7)) << 4));
}

__device__ __forceinline__ uint32_t pk(float lo, float hi) {
    __nv_bfloat162 t = __floats2bfloat162_rn(lo, hi);
    return *reinterpret_cast<uint32_t*>(&t);
}

// ---------------------------------------------------------------------------
// Kernel 1: norms + bf16 materialization
// ---------------------------------------------------------------------------
__global__ __launch_bounds__(256) void k_prep(const float* __restrict__ x1,
                                              const float* __restrict__ x2) {
    const int row = blockIdx.x, tid = threadIdx.x;
    const float4* p1 = reinterpret_cast<const float4*>(x1) + (size_t)row * (Nn / 4);
    const float4* p2 = reinterpret_cast<const float4*>(x2) + (size_t)row * (Nn / 4);
    float s1 = 0.f, s2 = 0.f;
    #pragma unroll
    for (int i = 0; i < 4; i++) {
        float4 v = p1[tid + i * 256]; s1 += v.x*v.x + v.y*v.y + v.z*v.z + v.w*v.w;
        float4 w = p2[tid + i * 256]; s2 += w.x*w.x + w.y*w.y + w.z*w.z + w.w*w.w;
    }
    #pragma unroll
    for (int o = 16; o > 0; o >>= 1) {
        s1 += __shfl_down_sync(0xffffffffu, s1, o);
        s2 += __shfl_down_sync(0xffffffffu, s2, o);
    }
    __shared__ float sh1[8], sh2[8], bi1, bi2;
    if ((tid & 31) == 0) { sh1[tid >> 5] = s1; sh2[tid >> 5] = s2; }
    __syncthreads();
    if (tid == 0) {
        float t1 = 0.f, t2 = 0.f;
        #pragma unroll
        for (int i = 0; i < 8; i++) { t1 += sh1[i]; t2 += sh2[i]; }
        bi1 = 1.0f / fmaxf(sqrtf(t1), 1e-12f);
        bi2 = 1.0f / fmaxf(sqrtf(t2), 1e-12f);
        g_inv1[row] = bi1; g_inv2[row] = bi2;
    }
    __syncthreads();
    const float i1 = bi1, i2 = bi2;
    uint4* oS  = reinterpret_cast<uint4*>(g_S  + (size_t)row * Nn);
    uint4* oX1 = reinterpret_cast<uint4*>(g_X1 + (size_t)row * Nn);
    uint4* oX2 = reinterpret_cast<uint4*>(g_X2 + (size_t)row * Nn);
    #pragma unroll
    for (int i = 0; i < 2; i++) {
        int seg = tid + i * 256;
        float4 a = p1[seg * 2], b = p1[seg * 2 + 1];
        float4 c = p2[seg * 2], d = p2[seg * 2 + 1];
        uint4 u1 = { pk(a.x, a.y), pk(a.z, a.w), pk(b.x, b.y), pk(b.z, b.w) };
        uint4 u2 = { pk(c.x, c.y), pk(c.z, c.w), pk(d.x, d.y), pk(d.z, d.w) };
        uint4 us = { pk(a.x*i1 + c.x*i2, a.y*i1 + c.y*i2),
                     pk(a.z*i1 + c.z*i2, a.w*i1 + c.w*i2),
                     pk(b.x*i1 + d.x*i2, b.y*i1 + d.y*i2),
                     pk(b.z*i1 + d.z*i2, b.w*i1 + d.w*i2) };
        oX1[seg] = u1; oX2[seg] = u2; oS[seg] = us;
    }
}

// ---------------------------------------------------------------------------
// Kernel 2: GEMM1, split-K x2. CTA 128(c) x 64(d), K=2048 per half, KT=64.
// grid.x = (d-tile<<1) | khalf. Partials to g_L1/g_L1b (g_L2/g_L2b).
// ---------------------------------------------------------------------------
#define G1_STAGE 32768
#define G1_SMEM  (3 * G1_STAGE + 512)

__global__ __launch_bounds__(256, 2) void k_gemm1() {
    extern __shared__ __align__(128) char smem[];
    const uint32_t sb = smem_u32(smem);
    const int tid = threadIdx.x, lane = tid & 31, wid = tid >> 5;
    const int wc = wid >> 1, wd = wid & 1;
    const int b = blockIdx.z, c0 = blockIdx.y * 128;
    const int d0 = (blockIdx.x >> 1) * 64, kh = blockIdx.x & 1;

    float* invs = (float*)(smem + 3 * G1_STAGE);
    if (tid < 64) {
        invs[tid]      = g_inv1[b * Cc + d0 + tid];
        invs[64 + tid] = g_inv2[b * Cc + d0 + tid];
    }

    const size_t kOff = (size_t)kh * 4096;   // 32 k-chunks * 128B
    const char* gS = (const char*)(g_S  + (size_t)(b * Cc + c0) * Nn) + kOff;
    const char* gU = (const char*)(g_X1 + (size_t)(b * Cc + d0) * Nn) + kOff;
    const char* gV = (const char*)(g_X2 + (size_t)(b * Cc + d0) * Nn) + kOff;

    #define G1_LOAD(st, kt) do { \
        uint32_t s_ = sb + (uint32_t)(st) * G1_STAGE; \
        _Pragma("unroll") \
        for (int i_ = 0; i_ < 4; i_++) { \
            int id_ = i_ * 256 + tid, r_ = id_ >> 3, c_ = id_ & 7; \
            CP16(s_ + swz(r_, c_), gS + (size_t)r_ * 8192 + (size_t)(kt) * 128 + c_ * 16); \
        } \
        _Pragma("unroll") \
        for (int i_ = 0; i_ < 2; i_++) { \
            int id_ = i_ * 256 + tid, r_ = id_ >> 3, c_ = id_ & 7; \
            CP16(s_ + 16384 + swz(r_, c_), gU + (size_t)r_ * 8192 + (size_t)(kt) * 128 + c_ * 16); \
            CP16(s_ + 24576 + swz(r_, c_), gV + (size_t)r_ * 8192 + (size_t)(kt) * 128 + c_ * 16); \
        } \
    } while (0)

    float acc[2][2][4][4];
    #pragma unroll
    for (int o = 0; o < 2; o++)
        #pragma unroll
        for (int m = 0; m < 2; m++)
            #pragma unroll
            for (int n = 0; n < 4; n++)
                #pragma unroll
                for (int k = 0; k < 4; k++) acc[o][m][n][k] = 0.f;

    G1_LOAD(0, 0); CP_COMMIT();
    G1_LOAD(1, 1); CP_COMMIT();
    CP_WAIT1();
    __syncthreads();

    for (int it = 0; it < 32; it++) {
        const uint32_t stg = sb + (uint32_t)(it % 3) * G1_STAGE;
        #pragma unroll
        for (int ks = 0; ks < 4; ks++) {
            uint32_t a[2][4], b1f[4][2], b2f[4][2], r4[4];
            const int ch = ks * 2 + (lane >> 4);
            #pragma unroll
            for (int mt = 0; mt < 2; mt++) {
                int row = wc * 32 + mt * 16 + (lane & 15);
                ldsm4(a[mt], stg + swz(row, ch));
            }
            #pragma unroll
            for (int p = 0; p < 2; p++) {
                int row = wd * 32 + p * 16 + (lane & 15);
                ldsm4(r4, stg + 16384 + swz(row, ch));
                b1f[2*p][0] = r4[0]; b1f[2*p][1] = r4[2];
                b1f[2*p+1][0] = r4[1]; b1f[2*p+1][1] = r4[3];
                ldsm4(r4, stg + 24576 + swz(row, ch));
                b2f[2*p][0] = r4[0]; b2f[2*p][1] = r4[2];
                b2f[2*p+1][0] = r4[1]; b2f[2*p+1][1] = r4[3];
            }
            #pragma unroll
            for (int mt = 0; mt < 2; mt++)
                #pragma unroll
                for (int nt = 0; nt < 4; nt++) {
                    mma16816(acc[0][mt][nt], a[mt], b1f[nt]);
                    mma16816(acc[1][mt][nt], a[mt], b2f[nt]);
                }
        }
        if (it + 2 < 32) G1_LOAD((it + 2) % 3, it + 2);
        CP_COMMIT();
        CP_WAIT1();
        __syncthreads();
    }

    const int crow = b * Cc + c0 + wc * 32 + (lane >> 2);
    #pragma unroll
    for (int o = 0; o < 2; o++) {
        float* L = o ? (kh ? g_L2b : g_L2) : (kh ? g_L1b : g_L1);
        #pragma unroll
        for (int mt = 0; mt < 2; mt++)
            #pragma unroll
            for (int nt = 0; nt < 4; nt++) {
                int dl = wd * 32 + nt * 8 + (lane & 3) * 2;
                float s0 = invs[o * 64 + dl], s1 = invs[o * 64 + dl + 1];
                float* p = L + (size_t)(crow + mt * 16) * Cc + d0 + dl;
                *(float2*)p = make_float2(acc[o][mt][nt][0] * s0, acc[o][mt][nt][1] * s1);
                *(float2*)(p + 8 * Cc) = make_float2(acc[o][mt][nt][2] * s0, acc[o][mt][nt][3] * s1);
            }
    }
    #undef G1_LOAD
}

// ---------------------------------------------------------------------------
// Kernel 3: softmax( L + Lb ) -> bf16 attn
// ---------------------------------------------------------------------------
__global__ __launch_bounds__(256) void k_softmax() {
    const int row = blockIdx.x, tid = threadIdx.x;
    const size_t idx = (size_t)row * Cc + tid;
    float v = blockIdx.y ? (g_L2[idx] + g_L2b[idx]) : (g_L1[idx] + g_L1b[idx]);
    __nv_bfloat16* A = (blockIdx.y ? g_A2 : g_A1) + (size_t)row * Cc;
    __shared__ float sh[8], bc;
    float m = v;
    #pragma unroll
    for (int o = 16; o > 0; o >>= 1) m = fmaxf(m, __shfl_xor_sync(0xffffffffu, m, o));
    if ((tid & 31) == 0) sh[tid >> 5] = m;
    __syncthreads();
    if (tid == 0) {
        float t = sh[0];
        #pragma unroll
        for (int i = 1; i < 8; i++) t = fmaxf(t, sh[i]);
        bc = t;
    }
    __syncthreads();
    float e = expf(v - bc);
    __syncthreads();
    float s = e;
    #pragma unroll
    for (int o = 16; o > 0; o >>= 1) s += __shfl_xor_sync(0xffffffffu, s, o);
    if ((tid & 31) == 0) sh[tid >> 5] = s;
    __syncthreads();
    if (tid == 0) {
        float t = 0.f;
        #pragma unroll
        for (int i = 0; i < 8; i++) t += sh[i];
        bc = t;
    }
    __syncthreads();
    A[tid] = __float2bfloat16(e / bc);
}

// ---------------------------------------------------------------------------
// Kernel 4: GEMM2. CTA 128(q) x 64(n), K=256, KT=64, 2 stages (96KB) so
// 2 CTAs/SM. 8 warps as 4(q) x 2(n), warp tile 32q x 32n.
//   D[q,n] = sum_d A1[q,d]*X1[d,n] + A2[q,d]*X2[d,n]
//   out[b, n*256+q] = D + x1 + x2   (SMEM [n][q] restage, coalesced)
// ---------------------------------------------------------------------------
#define G2_STAGE 49152
#define G2_SMEM  (2 * G2_STAGE)

__global__ __launch_bounds__(256, 2) void k_gemm2(const float* __restrict__ x1,
                                                  const float* __restrict__ x2,
                                                  float* __restrict__ out) {
    extern __shared__ __align__(128) char smem[];
    const uint32_t sb = smem_u32(smem);
    const int tid = threadIdx.x, lane = tid & 31, wid = tid >> 5;
    const int wq = wid >> 1, wn = wid & 1;
    const int b = blockIdx.z, q0 = blockIdx.y * 128, n0 = blockIdx.x * 64;

    const char* gA1 = (const char*)(g_A1 + (size_t)(b * Cc + q0) * Cc);
    const char* gA2 = (const char*)(g_A2 + (size_t)(b * Cc + q0) * Cc);
    const char* gX1 = (const char*)(g_X1 + (size_t)(b * Cc) * Nn) + (size_t)n0 * 2;
    const char* gX2 = (const char*)(g_X2 + (size_t)(b * Cc) * Nn) + (size_t)n0 * 2;

    // Stage: A1 [128][128B] @0, A2 @16384, X1 [64][128B] @32768, X2 @40960
    #define G2_LOAD(st, kt) do { \
        uint32_t s_ = sb + (uint32_t)(st) * G2_STAGE; \
        _Pragma("unroll") \
        for (int i_ = 0; i_ < 4; i_++) { \
            int id_ = i_ * 256 + tid, r_ = id_ >> 3, c_ = id_ & 7; \
            size_t go_ = (size_t)r_ * 512 + (size_t)(kt) * 128 + c_ * 16; \
            CP16(s_ + swz(r_, c_), gA1 + go_); \
            CP16(s_ + 16384 + swz(r_, c_), gA2 + go_); \
        } \
        _Pragma("unroll") \
        for (int i_ = 0; i_ < 2; i_++) { \
            int id_ = i_ * 256 + tid, r_ = id_ >> 3, c_ = id_ & 7; \
            size_t go_ = (size_t)((kt) * 64 + r_) * 8192 + c_ * 16; \
            CP16(s_ + 32768 + swz(r_, c_), gX1 + go_); \
            CP16(s_ + 40960 + swz(r_, c_), gX2 + go_); \
        } \
    } while (0)

    float acc[2][4][4];
    #pragma unroll
    for (int m = 0; m < 2; m++)
        #pragma unroll
        for (int n = 0; n < 4; n++)
            #pragma unroll
            for (int k = 0; k < 4; k++) acc[m][n][k] = 0.f;

    G2_LOAD(0, 0); CP_COMMIT();

    for (int it = 0; it < 4; it++) {
        if (it + 1 < 4) { G2_LOAD((it + 1) & 1, it + 1); CP_COMMIT(); CP_WAIT1(); }
        else            { CP_WAIT0(); }
        __syncthreads();
        const uint32_t stg = sb + (uint32_t)(it & 1) * G2_STAGE;
        #pragma unroll
        for (int ks = 0; ks < 4; ks++) {
            uint32_t a1[2][4], a2[2][4], bx1[4][2], bx2[4][2], r4[4];
            const int ch = ks * 2 + (lane >> 4);
            #pragma unroll
            for (int mt = 0; mt < 2; mt++) {
                int row = wq * 32 + mt * 16 + (lane & 15);
                ldsm4(a1[mt], stg + swz(row, ch));
                ldsm4(a2[mt], stg + 16384 + swz(row, ch));
            }
            #pragma unroll
            for (int p = 0; p < 2; p++) {
                int drow = ks * 16 + (lane & 15);
                int xch = 4 * wn + 2 * p + (lane >> 4);
                ldsm4t(r4, stg + 32768 + swz(drow, xch));
                bx1[2*p][0] = r4[0]; bx1[2*p][1] = r4[1];
                bx1[2*p+1][0] = r4[2]; bx1[2*p+1][1] = r4[3];
                ldsm4t(r4, stg + 40960 + swz(drow, xch));
                bx2[2*p][0] = r4[0]; bx2[2*p][1] = r4[1];
                bx2[2*p+1][0] = r4[2]; bx2[2*p+1][1] = r4[3];
            }
            #pragma unroll
            for (int mt = 0; mt < 2; mt++)
                #pragma unroll
                for (int nt = 0; nt < 4; nt++) {
                    mma16816(acc[mt][nt], a1[mt], bx1[nt]);
                    mma16816(acc[mt][nt], a2[mt], bx2[nt]);
                }
        }
        __syncthreads();
    }

    // Epilogue: restage [64 n][132 q] fp32 (single phase, all warps disjoint)
    float* eps = (float*)smem;
    #pragma unroll
    for (int mt = 0; mt < 2; mt++)
        #pragma unroll
        for (int nt = 0; nt < 4; nt++) {
            int qL = wq * 32 + mt * 16 + (lane >> 2);
            int rn = wn * 32 + nt * 8 + (lane & 3) * 2;
            eps[rn * 132 + qL]           = acc[mt][nt][0];
            eps[(rn + 1) * 132 + qL]     = acc[mt][nt][1];
            eps[rn * 132 + qL + 8]       = acc[mt][nt][2];
            eps[(rn + 1) * 132 + qL + 8] = acc[mt][nt][3];
        }
    __syncthreads();
    #pragma unroll
    for (int i = 0; i < 8; i++) {
        int slot = tid + i * 256;                 // 0..2047
        int row = slot >> 5, qi = slot & 31;
        size_t idx = ((size_t)b << 20) + (size_t)(n0 + row) * 256 + q0 + qi * 4;
        float4 d4 = *(const float4*)&eps[row * 132 + qi * 4];
        float4 ra = *(const float4*)(x1 + idx);
        float4 rb = *(const float4*)(x2 + idx);
        d4.x += ra.x + rb.x; d4.y += ra.y + rb.y;
        d4.z += ra.z + rb.z; d4.w += ra.w + rb.w;
        *(float4*)(out + idx) = d4;
    }
    #undef G2_LOAD
}

// ---------------------------------------------------------------------------
extern "C" void kernel_launch(void* const* d_in, const int* in_sizes, int n_in,
                              void* d_out, int out_size) {
    const float* x1 = (const float*)d_in[0];
    const float* x2 = (const float*)d_in[1];
    float* out = (float*)d_out;

    cudaFuncSetAttribute(k_gemm1, cudaFuncAttributeMaxDynamicSharedMemorySize, G1_SMEM);
    cudaFuncSetAttribute(k_gemm2, cudaFuncAttributeMaxDynamicSharedMemorySize, G2_SMEM);

    k_prep<<<Bb * Cc, 256>>>(x1, x2);
    k_gemm1<<<dim3(8, 2, Bb), 256, G1_SMEM>>>();
    k_softmax<<<dim3(Bb * Cc, 2), 256>>>();
    k_gemm2<<<dim3(Nn / 64, 2, Bb), 256, G2_SMEM>>>(x1, x2, out);
}